// round 14
// baseline (speedup 1.0000x reference)
#include <cuda_runtime.h>
#include <stdint.h>

#define R_TOT 524288
#define NE    33554432
#define ONEB  0x01010101
#define FMG   12582912.0f
#define EW_GRID 2368

struct Params {
    float s_x, zp_x, s_h, zp_h, s_c, zp_c, s_cat, zp_cat;
    float r_x, r_h, r_c, r_cat;
    float alpha[4];
    float bdq[256];
    int   zpw_i[4], zpc_i;
    float sG[4], zpG[4], sA[4], zpA[4];
    float rG[4], rA[4];
    float c1G[4], c2G[4];
    float s_fc, zp_fc, s_ic, zp_ic, s_cn, zp_cn, s_t, zp_t, s_hn, zp_hn;
    float r_fc, r_ic, r_cn, r_t, r_hn;
};

__device__ Params   g_p;
__device__ unsigned g_mm[22];
__device__ unsigned g_ctr[5];
__device__ int8_t   g_wq[256 * 128];
__device__ int      g_const[256];
__device__ float    g_G[134217728];      // gate pre-activations [row][256] (512 MB)
__device__ int8_t   g_act[4][NE];
__device__ int8_t   g_cq[NE];
__device__ int8_t   g_tq[NE];

// ---------- helpers ----------
__device__ __forceinline__ unsigned fenc(float f) {
    unsigned u = __float_as_uint(f);
    return (u & 0x80000000u) ? ~u : (u | 0x80000000u);
}
__device__ __forceinline__ float fdec(unsigned u) {
    return __uint_as_float((u & 0x80000000u) ? (u & 0x7fffffffu) : ~u);
}
__device__ __forceinline__ float clip128(float x) { return fminf(fmaxf(x, -128.f), 127.f); }
__device__ __forceinline__ float quant_qm(float v, float rs, float zp) {
    float x = clip128(__fmaf_rn(v, rs, zp));
    return __fadd_rn(__fadd_rn(x, FMG), -FMG);
}
__device__ __forceinline__ uint32_t quant_qb(float v, float rs, float zp) {
    float x = clip128(__fmaf_rn(v, rs, zp));
    return __float_as_uint(__fadd_rn(x, FMG));
}
__device__ __forceinline__ float fqvm(float v, float s, float rs, float zp) {
    return __fmul_rn(quant_qm(v, rs, zp) - zp, s);
}
__device__ __forceinline__ void mkparams(float mnr, float mxr, float* s, float* zp) {
    float mn = fminf(mnr, 0.f), mx = fmaxf(mxr, 0.f);
    float sc = fmaxf(__fdiv_rn(mx - mn, 255.f), 1e-8f);
    float z  = rintf(-128.f - __fdiv_rn(mn, sc));
    *s = sc; *zp = fminf(fmaxf(z, -128.f), 127.f);
}
#define HSIG_C 0.16666667f
__device__ __forceinline__ float hsig(float v) {
    return fminf(fmaxf(__fadd_rn(__fmul_rn(v, HSIG_C), 0.5f), 0.f), 1.f);
}
__device__ __forceinline__ float htanh(float v) { return fminf(fmaxf(v, -1.f), 1.f); }

__device__ __forceinline__ void block_minmax(float mn, float mx, unsigned* gmin, unsigned* gmax) {
    #pragma unroll
    for (int o = 16; o; o >>= 1) {
        mn = fminf(mn, __shfl_xor_sync(0xffffffffu, mn, o));
        mx = fmaxf(mx, __shfl_xor_sync(0xffffffffu, mx, o));
    }
    __shared__ float smn[8], smx[8];
    int w = threadIdx.x >> 5, nw = blockDim.x >> 5;
    __syncthreads();
    if ((threadIdx.x & 31) == 0) { smn[w] = mn; smx[w] = mx; }
    __syncthreads();
    if (threadIdx.x == 0) {
        for (int i = 1; i < nw; i++) { mn = fminf(mn, smn[i]); mx = fmaxf(mx, smx[i]); }
        atomicMin(gmin, fenc(mn)); atomicMax(gmax, fenc(mx));
    }
    __syncthreads();
}
__device__ __forceinline__ float2 block_reduce_pair(float mn, float mx) {
    #pragma unroll
    for (int o = 16; o; o >>= 1) {
        mn = fminf(mn, __shfl_xor_sync(0xffffffffu, mn, o));
        mx = fmaxf(mx, __shfl_xor_sync(0xffffffffu, mx, o));
    }
    __shared__ float smn[8], smx[8];
    __shared__ float2 res;
    int w = threadIdx.x >> 5, nw = blockDim.x >> 5;
    __syncthreads();
    if ((threadIdx.x & 31) == 0) { smn[w] = mn; smx[w] = mx; }
    __syncthreads();
    if (threadIdx.x == 0) {
        for (int i = 1; i < nw; i++) { mn = fminf(mn, smn[i]); mx = fmaxf(mx, smx[i]); }
        res = make_float2(mn, mx);
    }
    __syncthreads();
    return res;
}
__device__ __forceinline__ bool last_block(unsigned* ctr) {
    __shared__ int amLast;
    __threadfence();
    if (threadIdx.x == 0)
        amLast = (atomicAdd(ctr, 1u) == gridDim.x - 1u);
    __syncthreads();
    return amLast != 0;
}

__device__ __forceinline__ void mma_s8(int* c, uint32_t a0, uint32_t a1, uint32_t a2,
                                       uint32_t a3, uint32_t b0, uint32_t b1) {
    asm volatile(
        "mma.sync.aligned.m16n8k32.row.col.s32.s8.s8.s32 "
        "{%0,%1,%2,%3}, {%4,%5,%6,%7}, {%8,%9}, {%0,%1,%2,%3};\n"
        : "+r"(c[0]), "+r"(c[1]), "+r"(c[2]), "+r"(c[3])
        : "r"(a0), "r"(a1), "r"(a2), "r"(a3), "r"(b0), "r"(b1));
}
__device__ __forceinline__ void ldsm_x4(uint32_t& r0, uint32_t& r1, uint32_t& r2,
                                        uint32_t& r3, uint32_t addr) {
    asm volatile("ldmatrix.sync.aligned.m8n8.x4.shared.b16 {%0,%1,%2,%3}, [%4];"
                 : "=r"(r0), "=r"(r1), "=r"(r2), "=r"(r3) : "r"(addr));
}
__device__ __forceinline__ void ldsm_x2(uint32_t& r0, uint32_t& r1, uint32_t addr) {
    asm volatile("ldmatrix.sync.aligned.m8n8.x2.shared.b16 {%0,%1}, [%2];"
                 : "=r"(r0), "=r"(r1) : "r"(addr));
}

// ---------- scalar param bodies ----------
__device__ void p2_body() {
    for (int g = 0; g < 4; g++) {
        float mn = fdec(g_mm[6 + 2 * g]), mx = fdec(g_mm[7 + 2 * g]);
        mkparams(mn, mx, &g_p.sG[g], &g_p.zpG[g]);
        g_p.rG[g] = __fdiv_rn(1.f, g_p.sG[g]);
        float lo = fqvm(mn, g_p.sG[g], g_p.rG[g], g_p.zpG[g]);
        float hi = fqvm(mx, g_p.sG[g], g_p.rG[g], g_p.zpG[g]);
        float amin, amax;
        if (g < 3) { amin = hsig(lo); amax = hsig(hi); }
        else       { amin = htanh(lo); amax = htanh(hi); }
        mkparams(amin, amax, &g_p.sA[g], &g_p.zpA[g]);
        g_p.rA[g] = __fdiv_rn(1.f, g_p.sA[g]);
        if (g < 3) {
            g_p.c1G[g] = __fmul_rn(g_p.sG[g], HSIG_C);
            g_p.c2G[g] = __fadd_rn(0.5f, -__fmul_rn(g_p.zpG[g], g_p.c1G[g]));
        } else {
            g_p.c1G[g] = g_p.sG[g];
            g_p.c2G[g] = -__fmul_rn(g_p.zpG[g], g_p.sG[g]);
        }
    }
}
__device__ void p3_body() {
    mkparams(fdec(g_mm[14]), fdec(g_mm[15]), &g_p.s_fc, &g_p.zp_fc);
    mkparams(fdec(g_mm[16]), fdec(g_mm[17]), &g_p.s_ic, &g_p.zp_ic);
    g_p.r_fc = __fdiv_rn(1.f, g_p.s_fc);
    g_p.r_ic = __fdiv_rn(1.f, g_p.s_ic);
}
__device__ void p4_body() {
    float mn = fdec(g_mm[18]), mx = fdec(g_mm[19]);
    mkparams(mn, mx, &g_p.s_cn, &g_p.zp_cn);
    g_p.r_cn = __fdiv_rn(1.f, g_p.s_cn);
    float lo = htanh(fqvm(mn, g_p.s_cn, g_p.r_cn, g_p.zp_cn));
    float hi = htanh(fqvm(mx, g_p.s_cn, g_p.r_cn, g_p.zp_cn));
    mkparams(lo, hi, &g_p.s_t, &g_p.zp_t);
    g_p.r_t = __fdiv_rn(1.f, g_p.s_t);
}
__device__ void p5_body() {
    mkparams(fdec(g_mm[20]), fdec(g_mm[21]), &g_p.s_hn, &g_p.zp_hn);
    g_p.r_hn = __fdiv_rn(1.f, g_p.s_hn);
}

// ---------- K0 ----------
__global__ void k_init() {
    int t = threadIdx.x;
    if (t < 11) { g_mm[2 * t] = fenc(1e30f); g_mm[2 * t + 1] = fenc(-1e30f); }
    if (t < 5) g_ctr[t] = 0u;
}

// ---------- K1: minmax of x,h,c ; last block runs the params body ----------
__global__ void k_minmax3(const float* __restrict__ x, const float* __restrict__ h,
                          const float* __restrict__ c,
                          const float* __restrict__ Wi, const float* __restrict__ bi,
                          const float* __restrict__ Wf, const float* __restrict__ bf,
                          const float* __restrict__ Wo, const float* __restrict__ bo,
                          const float* __restrict__ Wc, const float* __restrict__ bc) {
    const float* arrs[3] = {x, h, c};
    for (int a = 0; a < 3; a++) {
        float mn = 1e30f, mx = -1e30f;
        const float4* p = (const float4*)arrs[a];
        for (long i = blockIdx.x * blockDim.x + threadIdx.x; i < NE / 4;
             i += (long)gridDim.x * blockDim.x) {
            float4 v = p[i];
            mn = fminf(fminf(fminf(mn, v.x), v.y), fminf(v.z, v.w));
            mx = fmaxf(fmaxf(fmaxf(mx, v.x), v.y), fmaxf(v.z, v.w));
        }
        block_minmax(mn, mx, &g_mm[2 * a], &g_mm[2 * a + 1]);
    }
    if (!last_block(&g_ctr[0])) return;
    __shared__ float sw, zw, rw, sb, zb, rb_;
    int t = threadIdx.x;
    if (t == 0) {
        g_ctr[0] = 0u;
        mkparams(fdec(g_mm[0]), fdec(g_mm[1]), &g_p.s_x, &g_p.zp_x);
        mkparams(fdec(g_mm[2]), fdec(g_mm[3]), &g_p.s_h, &g_p.zp_h);
        mkparams(fdec(g_mm[4]), fdec(g_mm[5]), &g_p.s_c, &g_p.zp_c);
        g_p.r_x = __fdiv_rn(1.f, g_p.s_x);
        g_p.r_h = __fdiv_rn(1.f, g_p.s_h);
        g_p.r_c = __fdiv_rn(1.f, g_p.s_c);
        float xlo = fqvm(fdec(g_mm[0]), g_p.s_x, g_p.r_x, g_p.zp_x);
        float xhi = fqvm(fdec(g_mm[1]), g_p.s_x, g_p.r_x, g_p.zp_x);
        float hlo = fqvm(fdec(g_mm[2]), g_p.s_h, g_p.r_h, g_p.zp_h);
        float hhi = fqvm(fdec(g_mm[3]), g_p.s_h, g_p.r_h, g_p.zp_h);
        mkparams(fminf(xlo, hlo), fmaxf(xhi, hhi), &g_p.s_cat, &g_p.zp_cat);
        g_p.r_cat = __fdiv_rn(1.f, g_p.s_cat);
        g_p.zpc_i = (int)g_p.zp_cat;
    }
    __syncthreads();
    const float* Wg[4] = {Wi, Wf, Wo, Wc};
    const float* bg[4] = {bi, bf, bo, bc};
    for (int g = 0; g < 4; g++) {
        float mn = 1e30f, mx = -1e30f;
        for (int i = t; i < 8192; i += 256) {
            float v = Wg[g][i];
            mn = fminf(mn, v); mx = fmaxf(mx, v);
        }
        float2 m = block_reduce_pair(mn, mx);
        if (t == 0) {
            mkparams(m.x, m.y, &sw, &zw);
            rw = __fdiv_rn(1.f, sw);
            g_p.alpha[g] = __fmul_rn(g_p.s_cat, sw);
            g_p.zpw_i[g] = (int)zw;
        }
        __syncthreads();
        for (int i = t; i < 8192; i += 256)
            g_wq[g * 8192 + i] = (int8_t)(int)quant_qm(Wg[g][i], rw, zw);
        mn = (t < 64) ? bg[g][t] : 1e30f;
        mx = (t < 64) ? bg[g][t] : -1e30f;
        m = block_reduce_pair(mn, mx);
        if (t == 0) { mkparams(m.x, m.y, &sb, &zb); rb_ = __fdiv_rn(1.f, sb); }
        __syncthreads();
        if (t < 64) g_p.bdq[g * 64 + t] = fqvm(bg[g][t], sb, rb_, zb);
        __syncthreads();
    }
    {
        int s = 0;
        const int8_t* wr = &g_wq[t * 128];
        for (int k = 0; k < 128; k++) s += wr[k];
        int g = t >> 6;
        g_const[t] = -g_p.zpc_i * s + 128 * g_p.zpc_i * g_p.zpw_i[g];
    }
}

#define W_BYTES   36864
#define W_STRB    144
#define CODE_STRW 36
#define DYN_A     (W_BYTES + 128 * CODE_STRW * 4)

// ---------- K3: single GEMM pass; last block runs p2 ----------
__global__ void __launch_bounds__(256) k_gemmA(const float* __restrict__ X,
                                               const float* __restrict__ H,
                                               const float* __restrict__ Cp) {
    extern __shared__ uint8_t dyn[];
    uint32_t* codes = (uint32_t*)(dyn + W_BYTES);
    __shared__ int   cosm[256];
    __shared__ float bosm[256];
    __shared__ float alsm[4];
    __shared__ int   zwsm[4];
    int t = threadIdx.x, lane = t & 31, w = t >> 5;

    {
        const uint4* wsrc = (const uint4*)&g_wq[t * 128];
        uint4* wdst = (uint4*)(dyn + t * W_STRB);
        #pragma unroll
        for (int i = 0; i < 8; i++) wdst[i] = wsrc[i];
    }
    cosm[t] = g_const[t];
    bosm[t] = g_p.bdq[t];
    if (t < 4) { alsm[t] = g_p.alpha[t]; zwsm[t] = g_p.zpw_i[t]; }

    float sx = g_p.s_x, rx = g_p.r_x, zx = g_p.zp_x;
    float sh = g_p.s_h, rh = g_p.r_h, zh = g_p.zp_h;
    float nzx = -__fmul_rn(zx, sx), nzh = -__fmul_rn(zh, sh);
    float rc = g_p.r_cat, zc = g_p.zp_cat;
    float rcc = g_p.r_c, zcc = g_p.zp_c;
    const float4* X4 = (const float4*)X;
    const float4* H4 = (const float4*)H;
    const float4* C4 = (const float4*)Cp;

    uint32_t Waddr = (uint32_t)__cvta_generic_to_shared(dyn);
    uint32_t Caddr = (uint32_t)__cvta_generic_to_shared(codes);
    uint32_t ldB_base = Waddr + (lane & 7) * W_STRB + ((lane >> 3) & 1) * 16;
    uint32_t ldA_base = Caddr + (w * 16 + (lane & 15)) * 144 + (lane >> 4) * 16;
    int rlo = w * 16 + (lane >> 2);

    float mnG[4], mxG[4];
    #pragma unroll
    for (int g = 0; g < 4; g++) { mnG[g] = 1e30f; mxG[g] = -1e30f; }
    __syncthreads();

    for (int tile = blockIdx.x; tile < R_TOT / 128; tile += gridDim.x) {
        long r0 = (long)tile * 128;
        #pragma unroll
        for (int i = 0; i < 8; i++) {
            int idx = t + i * 256;
            float4 v = C4[r0 * 16 + idx];
            uint32_t b0 = quant_qb(v.x, rcc, zcc);
            uint32_t b1 = quant_qb(v.y, rcc, zcc);
            uint32_t b2 = quant_qb(v.z, rcc, zcc);
            uint32_t b3 = quant_qb(v.w, rcc, zcc);
            ((uint32_t*)g_cq)[r0 * 16 + idx] =
                __byte_perm(__byte_perm(b0, b1, 0x0040),
                            __byte_perm(b2, b3, 0x0040), 0x5410);
        }
        #pragma unroll 4
        for (int rr = 0; rr < 16; rr++) {
            int lrow = w * 16 + rr;
            long row = r0 + lrow;
            float4 v = (lane < 16) ? X4[row * 16 + lane] : H4[row * 16 + lane - 16];
            float s0 = (lane < 16) ? sx : sh;
            float r0s = (lane < 16) ? rx : rh;
            float z0 = (lane < 16) ? zx : zh;
            float nz0 = (lane < 16) ? nzx : nzh;
            float c0 = quant_qm(v.x, r0s, z0), c1 = quant_qm(v.y, r0s, z0);
            float c2 = quant_qm(v.z, r0s, z0), c3 = quant_qm(v.w, r0s, z0);
            uint32_t b0 = quant_qb(__fmaf_rn(c0, s0, nz0), rc, zc);
            uint32_t b1 = quant_qb(__fmaf_rn(c1, s0, nz0), rc, zc);
            uint32_t b2 = quant_qb(__fmaf_rn(c2, s0, nz0), rc, zc);
            uint32_t b3 = quant_qb(__fmaf_rn(c3, s0, nz0), rc, zc);
            codes[lrow * CODE_STRW + lane] =
                __byte_perm(__byte_perm(b0, b1, 0x0040),
                            __byte_perm(b2, b3, 0x0040), 0x5410);
        }
        __syncthreads();
        if (t < 128) {
            const uint32_t* cr = &codes[t * CODE_STRW];
            int sum = 0;
            #pragma unroll
            for (int k = 0; k < 32; k++) sum = __dp4a((int)cr[k], ONEB, sum);
            codes[t * CODE_STRW + 32] = (uint32_t)sum;
        }
        __syncthreads();

        uint32_t a[16];
        #pragma unroll
        for (int kc = 0; kc < 4; kc++)
            ldsm_x4(a[kc * 4], a[kc * 4 + 1], a[kc * 4 + 2], a[kc * 4 + 3],
                    ldA_base + kc * 32);
        int rs_lo = (int)codes[rlo * CODE_STRW + 32];
        int rs_hi = (int)codes[(rlo + 8) * CODE_STRW + 32];
        long growL = (r0 + rlo) * 256, growH = (r0 + rlo + 8) * 256;

        #pragma unroll
        for (int g = 0; g < 4; g++) {
            float al = alsm[g];
            int   zwrs_lo = zwsm[g] * rs_lo, zwrs_hi = zwsm[g] * rs_hi;
            float mn = 1e30f, mx = -1e30f;
            #pragma unroll 4
            for (int ntg = 0; ntg < 8; ntg++) {
                int nt = g * 8 + ntg;
                int C[4] = {0, 0, 0, 0};
                #pragma unroll
                for (int kc = 0; kc < 4; kc++) {
                    uint32_t b0, b1;
                    ldsm_x2(b0, b1, ldB_base + nt * (8 * W_STRB) + kc * 32);
                    mma_s8(C, a[kc * 4], a[kc * 4 + 1], a[kc * 4 + 2], a[kc * 4 + 3],
                           b0, b1);
                }
                int col0 = nt * 8 + 2 * (lane & 3);
                int co0 = cosm[col0], co1 = cosm[col0 + 1];
                float bo0 = bosm[col0], bo1 = bosm[col0 + 1];
                float G0 = __fmaf_rn(__int2float_rn(C[0] + co0 - zwrs_lo), al, bo0);
                float G1 = __fmaf_rn(__int2float_rn(C[1] + co1 - zwrs_lo), al, bo1);
                float G2 = __fmaf_rn(__int2float_rn(C[2] + co0 - zwrs_hi), al, bo0);
                float G3 = __fmaf_rn(__int2float_rn(C[3] + co1 - zwrs_hi), al, bo1);
                *(float2*)&g_G[growL + col0] = make_float2(G0, G1);
                *(float2*)&g_G[growH + col0] = make_float2(G2, G3);
                mn = fminf(mn, fminf(fminf(G0, G1), fminf(G2, G3)));
                mx = fmaxf(mx, fmaxf(fmaxf(G0, G1), fmaxf(G2, G3)));
            }
            mnG[g] = fminf(mnG[g], mn);
            mxG[g] = fmaxf(mxG[g], mx);
        }
        __syncthreads();
    }
    #pragma unroll
    for (int g = 0; g < 4; g++) {
        float mn = mnG[g], mx = mxG[g];
        #pragma unroll
        for (int o = 16; o; o >>= 1) {
            mn = fminf(mn, __shfl_xor_sync(0xffffffffu, mn, o));
            mx = fmaxf(mx, __shfl_xor_sync(0xffffffffu, mx, o));
        }
        if (lane == 0) {
            atomicMin(&g_mm[6 + 2 * g], fenc(mn));
            atomicMax(&g_mm[7 + 2 * g], fenc(mx));
        }
    }
    if (last_block(&g_ctr[1]) && t == 0) { g_ctr[1] = 0u; p2_body(); }
}

// ---------- K5: activations from stored G; fc/ic minmax; last block runs p3 ----------
__global__ void __launch_bounds__(256, 5) k_act() {
    float rG[4], zG[4], c1[4], c2[4], rA[4], zA[4], sA[4];
    #pragma unroll
    for (int g = 0; g < 4; g++) {
        rG[g] = g_p.rG[g]; zG[g] = g_p.zpG[g];
        c1[g] = g_p.c1G[g]; c2[g] = g_p.c2G[g];
        rA[g] = g_p.rA[g]; zA[g] = g_p.zpA[g];
        sA[g] = g_p.sA[g];
    }
    float scc = g_p.s_c, zcc = g_p.zp_c;
    float mn1 = 1e30f, mx1 = -1e30f, mn2 = 1e30f, mx2 = -1e30f;
    for (long i = blockIdx.x * blockDim.x + threadIdx.x; i < NE / 4;
         i += (long)gridDim.x * blockDim.x) {
        long row = i >> 4;
        int h0 = (int)(i & 15) * 4;
        char4 qc = ((const char4*)g_cq)[i];
        int ccode[4] = {qc.x, qc.y, qc.z, qc.w};
        float acode[4][4];
        #pragma unroll
        for (int g = 0; g < 4; g++) {
            float4 G4 = *(const float4*)&g_G[row * 256 + g * 64 + h0];
            float gv[4] = {G4.x, G4.y, G4.z, G4.w};
            float aLo = (g == 3) ? -1.f : 0.f;
            uint32_t q[4];
            #pragma unroll
            for (int j = 0; j < 4; j++) {
                float cf = quant_qm(gv[j], rG[g], zG[g]);
                float a = fminf(fmaxf(__fmaf_rn(cf, c1[g], c2[g]), aLo), 1.f);
                float code = quant_qm(a, rA[g], zA[g]);
                acode[g][j] = code;
                q[j] = __float_as_uint(__fadd_rn(code, FMG));
            }
            ((uint32_t*)g_act[g])[i] =
                __byte_perm(__byte_perm(q[0], q[1], 0x0040),
                            __byte_perm(q[2], q[3], 0x0040), 0x5410);
        }
        #pragma unroll
        for (int j = 0; j < 4; j++) {
            float fv = __fmul_rn(acode[1][j] - zA[1], sA[1]);
            float iv = __fmul_rn(acode[0][j] - zA[0], sA[0]);
            float gv = __fmul_rn(acode[3][j] - zA[3], sA[3]);
            float cd = __fmul_rn((float)ccode[j] - zcc, scc);
            float fc = __fmul_rn(fv, cd);
            float ic = __fmul_rn(iv, gv);
            mn1 = fminf(mn1, fc); mx1 = fmaxf(mx1, fc);
            mn2 = fminf(mn2, ic); mx2 = fmaxf(mx2, ic);
        }
    }
    block_minmax(mn1, mx1, &g_mm[14], &g_mm[15]);
    block_minmax(mn2, mx2, &g_mm[16], &g_mm[17]);
    if (last_block(&g_ctr[2]) && threadIdx.x == 0) { g_ctr[2] = 0u; p3_body(); }
}

// ---------- K7: minmax of fq(fc)+fq(ic); last block runs p4 ----------
__global__ void __launch_bounds__(256, 5) k_pre() {
    float sAi = g_p.sA[0], zAi = g_p.zpA[0], sAf = g_p.sA[1], zAf = g_p.zpA[1];
    float sAg = g_p.sA[3], zAg = g_p.zpA[3], scc = g_p.s_c, zcc = g_p.zp_c;
    float sfc = g_p.s_fc, rfc = g_p.r_fc, zfc = g_p.zp_fc;
    float sic = g_p.s_ic, ric = g_p.r_ic, zic = g_p.zp_ic;
    float mn = 1e30f, mx = -1e30f;
    for (long i = blockIdx.x * blockDim.x + threadIdx.x; i < NE / 4;
         i += (long)gridDim.x * blockDim.x) {
        char4 qi = ((const char4*)g_act[0])[i];
        char4 qf = ((const char4*)g_act[1])[i];
        char4 qg = ((const char4*)g_act[3])[i];
        char4 qc = ((const char4*)g_cq)[i];
        int ii[4] = {qi.x, qi.y, qi.z, qi.w}, ff[4] = {qf.x, qf.y, qf.z, qf.w};
        int gg[4] = {qg.x, qg.y, qg.z, qg.w}, cc[4] = {qc.x, qc.y, qc.z, qc.w};
        #pragma unroll
        for (int j = 0; j < 4; j++) {
            float fv = __fmul_rn((float)ff[j] - zAf, sAf);
            float iv = __fmul_rn((float)ii[j] - zAi, sAi);
            float gv = __fmul_rn((float)gg[j] - zAg, sAg);
            float cd = __fmul_rn((float)cc[j] - zcc, scc);
            float fcv = fqvm(__fmul_rn(fv, cd), sfc, rfc, zfc);
            float icv = fqvm(__fmul_rn(iv, gv), sic, ric, zic);
            float pre = __fadd_rn(fcv, icv);
            mn = fminf(mn, pre); mx = fmaxf(mx, pre);
        }
    }
    block_minmax(mn, mx, &g_mm[18], &g_mm[19]);
    if (last_block(&g_ctr[3]) && threadIdx.x == 0) { g_ctr[3] = 0u; p4_body(); }
}

// ---------- K9: c_next + t codes + o*t minmax; last block runs p5 ----------
__global__ void __launch_bounds__(256, 5) k_cnext(float* __restrict__ out_c) {
    float sAi = g_p.sA[0], zAi = g_p.zpA[0], sAf = g_p.sA[1], zAf = g_p.zpA[1];
    float sAo = g_p.sA[2], zAo = g_p.zpA[2], sAg = g_p.sA[3], zAg = g_p.zpA[3];
    float scc = g_p.s_c, zcc = g_p.zp_c;
    float sfc = g_p.s_fc, rfc = g_p.r_fc, zfc = g_p.zp_fc;
    float sic = g_p.s_ic, ric = g_p.r_ic, zic = g_p.zp_ic;
    float scn = g_p.s_cn, rcn = g_p.r_cn, zcn = g_p.zp_cn;
    float st = g_p.s_t, rt = g_p.r_t, zt = g_p.zp_t;
    float mn = 1e30f, mx = -1e30f;
    for (long i = blockIdx.x * blockDim.x + threadIdx.x; i < NE / 4;
         i += (long)gridDim.x * blockDim.x) {
        char4 qi = ((const char4*)g_act[0])[i];
        char4 qf = ((const char4*)g_act[1])[i];
        char4 qo = ((const char4*)g_act[2])[i];
        char4 qg = ((const char4*)g_act[3])[i];
        char4 qc = ((const char4*)g_cq)[i];
        int ii[4] = {qi.x, qi.y, qi.z, qi.w}, ff[4] = {qf.x, qf.y, qf.z, qf.w};
        int oo[4] = {qo.x, qo.y, qo.z, qo.w}, gg[4] = {qg.x, qg.y, qg.z, qg.w};
        int cc[4] = {qc.x, qc.y, qc.z, qc.w};
        float4 outc;
        float* oc = (float*)&outc;
        char4 tq4;
        int8_t* tqq = (int8_t*)&tq4;
        #pragma unroll
        for (int j = 0; j < 4; j++) {
            float fv = __fmul_rn((float)ff[j] - zAf, sAf);
            float iv = __fmul_rn((float)ii[j] - zAi, sAi);
            float gv = __fmul_rn((float)gg[j] - zAg, sAg);
            float cd = __fmul_rn((float)cc[j] - zcc, scc);
            float fcv = fqvm(__fmul_rn(fv, cd), sfc, rfc, zfc);
            float icv = fqvm(__fmul_rn(iv, gv), sic, ric, zic);
            float pre = __fadd_rn(fcv, icv);
            float cn = fqvm(pre, scn, rcn, zcn);
            oc[j] = cn;
            float tcodef = quant_qm(htanh(cn), rt, zt);
            tqq[j] = (int8_t)(int)tcodef;
            float tv = __fmul_rn(tcodef - zt, st);
            float ov = __fmul_rn((float)oo[j] - zAo, sAo);
            float hp = __fmul_rn(ov, tv);
            mn = fminf(mn, hp); mx = fmaxf(mx, hp);
        }
        ((float4*)out_c)[i] = outc;
        ((char4*)g_tq)[i] = tq4;
    }
    block_minmax(mn, mx, &g_mm[20], &g_mm[21]);
    if (last_block(&g_ctr[4]) && threadIdx.x == 0) { g_ctr[4] = 0u; p5_body(); }
}

// ---------- K11 ----------
__global__ void __launch_bounds__(256, 5) k_hnext(float* __restrict__ out_h) {
    float sAo = g_p.sA[2], zAo = g_p.zpA[2], st = g_p.s_t, zt = g_p.zp_t;
    float shn = g_p.s_hn, rhn = g_p.r_hn, zhn = g_p.zp_hn;
    for (long i = blockIdx.x * blockDim.x + threadIdx.x; i < NE / 4;
         i += (long)gridDim.x * blockDim.x) {
        char4 qo = ((const char4*)g_act[2])[i];
        char4 qt = ((const char4*)g_tq)[i];
        int oo[4] = {qo.x, qo.y, qo.z, qo.w}, tt[4] = {qt.x, qt.y, qt.z, qt.w};
        float4 outh;
        float* oh = (float*)&outh;
        #pragma unroll
        for (int j = 0; j < 4; j++) {
            float ov = __fmul_rn((float)oo[j] - zAo, sAo);
            float tv = __fmul_rn((float)tt[j] - zt, st);
            oh[j] = fqvm(__fmul_rn(ov, tv), shn, rhn, zhn);
        }
        ((float4*)out_h)[i] = outh;
    }
}

extern "C" void kernel_launch(void* const* d_in, const int* in_sizes, int n_in,
                              void* d_out, int out_size) {
    const float* x  = (const float*)d_in[0];
    const float* h  = (const float*)d_in[1];
    const float* c  = (const float*)d_in[2];
    const float* Wi = (const float*)d_in[3];
    const float* bi = (const float*)d_in[4];
    const float* Wf = (const float*)d_in[5];
    const float* bf = (const float*)d_in[6];
    const float* Wo = (const float*)d_in[7];
    const float* bo = (const float*)d_in[8];
    const float* Wc = (const float*)d_in[9];
    const float* bc = (const float*)d_in[10];
    float* out_h = (float*)d_out;
    float* out_c = (float*)d_out + NE;

    static int attr_done = 0;
    if (!attr_done) {
        cudaFuncSetAttribute(k_gemmA, cudaFuncAttributeMaxDynamicSharedMemorySize, DYN_A);
        attr_done = 1;
    }

    k_init<<<1, 32>>>();
    k_minmax3<<<2048, 256>>>(x, h, c, Wi, bi, Wf, bf, Wo, bo, Wc, bc);
    k_gemmA<<<2048, 256, DYN_A>>>(x, h, c);
    k_act<<<EW_GRID, 256>>>();
    k_pre<<<EW_GRID, 256>>>();
    k_cnext<<<EW_GRID, 256>>>(out_c);
    k_hnext<<<EW_GRID, 256>>>(out_h);
}

// round 15
// speedup vs baseline: 1.0517x; 1.0517x over previous
#include <cuda_runtime.h>
#include <stdint.h>

#define R_TOT 524288
#define NE    33554432
#define ONEB  0x01010101
#define FMG   12582912.0f
#define EW_GRID 2368

struct Params {
    float s_x, zp_x, s_h, zp_h, s_c, zp_c, s_cat, zp_cat;
    float r_x, r_h, r_c, r_cat;
    float alpha[4];
    float bdq[256];
    int   zpw_i[4], zpc_i;
    float sG[4], zpG[4], sA[4], zpA[4];
    float rG[4], rA[4];
    float c1G[4], c2G[4];
    float s_fc, zp_fc, s_ic, zp_ic, s_cn, zp_cn, s_t, zp_t, s_hn, zp_hn;
    float r_fc, r_ic, r_cn, r_t, r_hn;
};

__device__ Params   g_p;
__device__ unsigned g_mm[22];
__device__ unsigned g_ctr[5];
__device__ int8_t   g_wq[256 * 128];
__device__ int      g_const[256];
__device__ float    g_G[134217728];      // gate pre-activations [row][256] (512 MB)
__device__ int8_t   g_act[4][NE];
__device__ int8_t   g_cq[NE];
__device__ int8_t   g_tq[NE];

// ---------- helpers ----------
__device__ __forceinline__ unsigned fenc(float f) {
    unsigned u = __float_as_uint(f);
    return (u & 0x80000000u) ? ~u : (u | 0x80000000u);
}
__device__ __forceinline__ float fdec(unsigned u) {
    return __uint_as_float((u & 0x80000000u) ? (u & 0x7fffffffu) : ~u);
}
__device__ __forceinline__ float clip128(float x) { return fminf(fmaxf(x, -128.f), 127.f); }
__device__ __forceinline__ float quant_qm(float v, float rs, float zp) {
    float x = clip128(__fmaf_rn(v, rs, zp));
    return __fadd_rn(__fadd_rn(x, FMG), -FMG);
}
__device__ __forceinline__ uint32_t quant_qb(float v, float rs, float zp) {
    float x = clip128(__fmaf_rn(v, rs, zp));
    return __float_as_uint(__fadd_rn(x, FMG));
}
__device__ __forceinline__ float fqvm(float v, float s, float rs, float zp) {
    return __fmul_rn(quant_qm(v, rs, zp) - zp, s);
}
__device__ __forceinline__ void mkparams(float mnr, float mxr, float* s, float* zp) {
    float mn = fminf(mnr, 0.f), mx = fmaxf(mxr, 0.f);
    float sc = fmaxf(__fdiv_rn(mx - mn, 255.f), 1e-8f);
    float z  = rintf(-128.f - __fdiv_rn(mn, sc));
    *s = sc; *zp = fminf(fmaxf(z, -128.f), 127.f);
}
#define HSIG_C 0.16666667f
__device__ __forceinline__ float hsig(float v) {
    return fminf(fmaxf(__fadd_rn(__fmul_rn(v, HSIG_C), 0.5f), 0.f), 1.f);
}
__device__ __forceinline__ float htanh(float v) { return fminf(fmaxf(v, -1.f), 1.f); }

__device__ __forceinline__ void block_minmax(float mn, float mx, unsigned* gmin, unsigned* gmax) {
    #pragma unroll
    for (int o = 16; o; o >>= 1) {
        mn = fminf(mn, __shfl_xor_sync(0xffffffffu, mn, o));
        mx = fmaxf(mx, __shfl_xor_sync(0xffffffffu, mx, o));
    }
    __shared__ float smn[8], smx[8];
    int w = threadIdx.x >> 5, nw = blockDim.x >> 5;
    __syncthreads();
    if ((threadIdx.x & 31) == 0) { smn[w] = mn; smx[w] = mx; }
    __syncthreads();
    if (threadIdx.x == 0) {
        for (int i = 1; i < nw; i++) { mn = fminf(mn, smn[i]); mx = fmaxf(mx, smx[i]); }
        atomicMin(gmin, fenc(mn)); atomicMax(gmax, fenc(mx));
    }
    __syncthreads();
}
__device__ __forceinline__ float2 block_reduce_pair(float mn, float mx) {
    #pragma unroll
    for (int o = 16; o; o >>= 1) {
        mn = fminf(mn, __shfl_xor_sync(0xffffffffu, mn, o));
        mx = fmaxf(mx, __shfl_xor_sync(0xffffffffu, mx, o));
    }
    __shared__ float smn[8], smx[8];
    __shared__ float2 res;
    int w = threadIdx.x >> 5, nw = blockDim.x >> 5;
    __syncthreads();
    if ((threadIdx.x & 31) == 0) { smn[w] = mn; smx[w] = mx; }
    __syncthreads();
    if (threadIdx.x == 0) {
        for (int i = 1; i < nw; i++) { mn = fminf(mn, smn[i]); mx = fmaxf(mx, smx[i]); }
        res = make_float2(mn, mx);
    }
    __syncthreads();
    return res;
}
__device__ __forceinline__ bool last_block(unsigned* ctr) {
    __shared__ int amLast;
    __threadfence();
    if (threadIdx.x == 0)
        amLast = (atomicAdd(ctr, 1u) == gridDim.x - 1u);
    __syncthreads();
    return amLast != 0;
}

__device__ __forceinline__ void mma_s8(int* c, uint32_t a0, uint32_t a1, uint32_t a2,
                                       uint32_t a3, uint32_t b0, uint32_t b1) {
    asm volatile(
        "mma.sync.aligned.m16n8k32.row.col.s32.s8.s8.s32 "
        "{%0,%1,%2,%3}, {%4,%5,%6,%7}, {%8,%9}, {%0,%1,%2,%3};\n"
        : "+r"(c[0]), "+r"(c[1]), "+r"(c[2]), "+r"(c[3])
        : "r"(a0), "r"(a1), "r"(a2), "r"(a3), "r"(b0), "r"(b1));
}
__device__ __forceinline__ void ldsm_x4(uint32_t& r0, uint32_t& r1, uint32_t& r2,
                                        uint32_t& r3, uint32_t addr) {
    asm volatile("ldmatrix.sync.aligned.m8n8.x4.shared.b16 {%0,%1,%2,%3}, [%4];"
                 : "=r"(r0), "=r"(r1), "=r"(r2), "=r"(r3) : "r"(addr));
}
__device__ __forceinline__ void ldsm_x2(uint32_t& r0, uint32_t& r1, uint32_t addr) {
    asm volatile("ldmatrix.sync.aligned.m8n8.x2.shared.b16 {%0,%1}, [%2];"
                 : "=r"(r0), "=r"(r1) : "r"(addr));
}

// ---------- scalar param bodies ----------
__device__ void p2_body() {
    for (int g = 0; g < 4; g++) {
        float mn = fdec(g_mm[6 + 2 * g]), mx = fdec(g_mm[7 + 2 * g]);
        mkparams(mn, mx, &g_p.sG[g], &g_p.zpG[g]);
        g_p.rG[g] = __fdiv_rn(1.f, g_p.sG[g]);
        float lo = fqvm(mn, g_p.sG[g], g_p.rG[g], g_p.zpG[g]);
        float hi = fqvm(mx, g_p.sG[g], g_p.rG[g], g_p.zpG[g]);
        float amin, amax;
        if (g < 3) { amin = hsig(lo); amax = hsig(hi); }
        else       { amin = htanh(lo); amax = htanh(hi); }
        mkparams(amin, amax, &g_p.sA[g], &g_p.zpA[g]);
        g_p.rA[g] = __fdiv_rn(1.f, g_p.sA[g]);
        if (g < 3) {
            g_p.c1G[g] = __fmul_rn(g_p.sG[g], HSIG_C);
            g_p.c2G[g] = __fadd_rn(0.5f, -__fmul_rn(g_p.zpG[g], g_p.c1G[g]));
        } else {
            g_p.c1G[g] = g_p.sG[g];
            g_p.c2G[g] = -__fmul_rn(g_p.zpG[g], g_p.sG[g]);
        }
    }
}
__device__ void p3_body() {
    mkparams(fdec(g_mm[14]), fdec(g_mm[15]), &g_p.s_fc, &g_p.zp_fc);
    mkparams(fdec(g_mm[16]), fdec(g_mm[17]), &g_p.s_ic, &g_p.zp_ic);
    g_p.r_fc = __fdiv_rn(1.f, g_p.s_fc);
    g_p.r_ic = __fdiv_rn(1.f, g_p.s_ic);
}
__device__ void p4_body() {
    float mn = fdec(g_mm[18]), mx = fdec(g_mm[19]);
    mkparams(mn, mx, &g_p.s_cn, &g_p.zp_cn);
    g_p.r_cn = __fdiv_rn(1.f, g_p.s_cn);
    float lo = htanh(fqvm(mn, g_p.s_cn, g_p.r_cn, g_p.zp_cn));
    float hi = htanh(fqvm(mx, g_p.s_cn, g_p.r_cn, g_p.zp_cn));
    mkparams(lo, hi, &g_p.s_t, &g_p.zp_t);
    g_p.r_t = __fdiv_rn(1.f, g_p.s_t);
}
__device__ void p5_body() {
    mkparams(fdec(g_mm[20]), fdec(g_mm[21]), &g_p.s_hn, &g_p.zp_hn);
    g_p.r_hn = __fdiv_rn(1.f, g_p.s_hn);
}

// ---------- K0 ----------
__global__ void k_init() {
    int t = threadIdx.x;
    if (t < 11) { g_mm[2 * t] = fenc(1e30f); g_mm[2 * t + 1] = fenc(-1e30f); }
    if (t < 5) g_ctr[t] = 0u;
}

// ---------- K1: minmax of x,h,c ; last block runs the params body ----------
__global__ void k_minmax3(const float* __restrict__ x, const float* __restrict__ h,
                          const float* __restrict__ c,
                          const float* __restrict__ Wi, const float* __restrict__ bi,
                          const float* __restrict__ Wf, const float* __restrict__ bf,
                          const float* __restrict__ Wo, const float* __restrict__ bo,
                          const float* __restrict__ Wc, const float* __restrict__ bc) {
    const float* arrs[3] = {x, h, c};
    for (int a = 0; a < 3; a++) {
        float mn = 1e30f, mx = -1e30f;
        const float4* p = (const float4*)arrs[a];
        for (long i = blockIdx.x * blockDim.x + threadIdx.x; i < NE / 4;
             i += (long)gridDim.x * blockDim.x) {
            float4 v = p[i];
            mn = fminf(fminf(fminf(mn, v.x), v.y), fminf(v.z, v.w));
            mx = fmaxf(fmaxf(fmaxf(mx, v.x), v.y), fmaxf(v.z, v.w));
        }
        block_minmax(mn, mx, &g_mm[2 * a], &g_mm[2 * a + 1]);
    }
    if (!last_block(&g_ctr[0])) return;
    __shared__ float sw, zw, rw, sb, zb, rb_;
    int t = threadIdx.x;
    if (t == 0) {
        g_ctr[0] = 0u;
        mkparams(fdec(g_mm[0]), fdec(g_mm[1]), &g_p.s_x, &g_p.zp_x);
        mkparams(fdec(g_mm[2]), fdec(g_mm[3]), &g_p.s_h, &g_p.zp_h);
        mkparams(fdec(g_mm[4]), fdec(g_mm[5]), &g_p.s_c, &g_p.zp_c);
        g_p.r_x = __fdiv_rn(1.f, g_p.s_x);
        g_p.r_h = __fdiv_rn(1.f, g_p.s_h);
        g_p.r_c = __fdiv_rn(1.f, g_p.s_c);
        float xlo = fqvm(fdec(g_mm[0]), g_p.s_x, g_p.r_x, g_p.zp_x);
        float xhi = fqvm(fdec(g_mm[1]), g_p.s_x, g_p.r_x, g_p.zp_x);
        float hlo = fqvm(fdec(g_mm[2]), g_p.s_h, g_p.r_h, g_p.zp_h);
        float hhi = fqvm(fdec(g_mm[3]), g_p.s_h, g_p.r_h, g_p.zp_h);
        mkparams(fminf(xlo, hlo), fmaxf(xhi, hhi), &g_p.s_cat, &g_p.zp_cat);
        g_p.r_cat = __fdiv_rn(1.f, g_p.s_cat);
        g_p.zpc_i = (int)g_p.zp_cat;
    }
    __syncthreads();
    const float* Wg[4] = {Wi, Wf, Wo, Wc};
    const float* bg[4] = {bi, bf, bo, bc};
    for (int g = 0; g < 4; g++) {
        float mn = 1e30f, mx = -1e30f;
        for (int i = t; i < 8192; i += 256) {
            float v = Wg[g][i];
            mn = fminf(mn, v); mx = fmaxf(mx, v);
        }
        float2 m = block_reduce_pair(mn, mx);
        if (t == 0) {
            mkparams(m.x, m.y, &sw, &zw);
            rw = __fdiv_rn(1.f, sw);
            g_p.alpha[g] = __fmul_rn(g_p.s_cat, sw);
            g_p.zpw_i[g] = (int)zw;
        }
        __syncthreads();
        for (int i = t; i < 8192; i += 256)
            g_wq[g * 8192 + i] = (int8_t)(int)quant_qm(Wg[g][i], rw, zw);
        mn = (t < 64) ? bg[g][t] : 1e30f;
        mx = (t < 64) ? bg[g][t] : -1e30f;
        m = block_reduce_pair(mn, mx);
        if (t == 0) { mkparams(m.x, m.y, &sb, &zb); rb_ = __fdiv_rn(1.f, sb); }
        __syncthreads();
        if (t < 64) g_p.bdq[g * 64 + t] = fqvm(bg[g][t], sb, rb_, zb);
        __syncthreads();
    }
    {
        int s = 0;
        const int8_t* wr = &g_wq[t * 128];
        for (int k = 0; k < 128; k++) s += wr[k];
        int g = t >> 6;
        g_const[t] = -g_p.zpc_i * s + 128 * g_p.zpc_i * g_p.zpw_i[g];
    }
}

#define W_BYTES   36864
#define W_STRB    144
#define CODE_STRW 36
#define DYN_A     (W_BYTES + 128 * CODE_STRW * 4)

// ---------- K3: single GEMM pass; last block runs p2 ----------
__global__ void __launch_bounds__(256) k_gemmA(const float* __restrict__ X,
                                               const float* __restrict__ H,
                                               const float* __restrict__ Cp) {
    extern __shared__ uint8_t dyn[];
    uint32_t* codes = (uint32_t*)(dyn + W_BYTES);
    __shared__ int   cosm[256];
    __shared__ float bosm[256];
    __shared__ float alsm[4];
    __shared__ int   zwsm[4];
    int t = threadIdx.x, lane = t & 31, w = t >> 5;

    {
        const uint4* wsrc = (const uint4*)&g_wq[t * 128];
        uint4* wdst = (uint4*)(dyn + t * W_STRB);
        #pragma unroll
        for (int i = 0; i < 8; i++) wdst[i] = wsrc[i];
    }
    cosm[t] = g_const[t];
    bosm[t] = g_p.bdq[t];
    if (t < 4) { alsm[t] = g_p.alpha[t]; zwsm[t] = g_p.zpw_i[t]; }

    float sx = g_p.s_x, rx = g_p.r_x, zx = g_p.zp_x;
    float sh = g_p.s_h, rh = g_p.r_h, zh = g_p.zp_h;
    float nzx = -__fmul_rn(zx, sx), nzh = -__fmul_rn(zh, sh);
    float rc = g_p.r_cat, zc = g_p.zp_cat;
    float rcc = g_p.r_c, zcc = g_p.zp_c;
    const float4* X4 = (const float4*)X;
    const float4* H4 = (const float4*)H;
    const float4* C4 = (const float4*)Cp;

    uint32_t Waddr = (uint32_t)__cvta_generic_to_shared(dyn);
    uint32_t Caddr = (uint32_t)__cvta_generic_to_shared(codes);
    uint32_t ldB_base = Waddr + (lane & 7) * W_STRB + ((lane >> 3) & 1) * 16;
    uint32_t ldA_base = Caddr + (w * 16 + (lane & 15)) * 144 + (lane >> 4) * 16;
    int rlo = w * 16 + (lane >> 2);

    float mnG[4], mxG[4];
    #pragma unroll
    for (int g = 0; g < 4; g++) { mnG[g] = 1e30f; mxG[g] = -1e30f; }
    __syncthreads();

    for (int tile = blockIdx.x; tile < R_TOT / 128; tile += gridDim.x) {
        long r0 = (long)tile * 128;
        #pragma unroll
        for (int i = 0; i < 8; i++) {
            int idx = t + i * 256;
            float4 v = C4[r0 * 16 + idx];
            uint32_t b0 = quant_qb(v.x, rcc, zcc);
            uint32_t b1 = quant_qb(v.y, rcc, zcc);
            uint32_t b2 = quant_qb(v.z, rcc, zcc);
            uint32_t b3 = quant_qb(v.w, rcc, zcc);
            ((uint32_t*)g_cq)[r0 * 16 + idx] =
                __byte_perm(__byte_perm(b0, b1, 0x0040),
                            __byte_perm(b2, b3, 0x0040), 0x5410);
        }
        #pragma unroll 4
        for (int rr = 0; rr < 16; rr++) {
            int lrow = w * 16 + rr;
            long row = r0 + lrow;
            float4 v = (lane < 16) ? X4[row * 16 + lane] : H4[row * 16 + lane - 16];
            float s0 = (lane < 16) ? sx : sh;
            float r0s = (lane < 16) ? rx : rh;
            float z0 = (lane < 16) ? zx : zh;
            float nz0 = (lane < 16) ? nzx : nzh;
            float c0 = quant_qm(v.x, r0s, z0), c1 = quant_qm(v.y, r0s, z0);
            float c2 = quant_qm(v.z, r0s, z0), c3 = quant_qm(v.w, r0s, z0);
            uint32_t b0 = quant_qb(__fmaf_rn(c0, s0, nz0), rc, zc);
            uint32_t b1 = quant_qb(__fmaf_rn(c1, s0, nz0), rc, zc);
            uint32_t b2 = quant_qb(__fmaf_rn(c2, s0, nz0), rc, zc);
            uint32_t b3 = quant_qb(__fmaf_rn(c3, s0, nz0), rc, zc);
            codes[lrow * CODE_STRW + lane] =
                __byte_perm(__byte_perm(b0, b1, 0x0040),
                            __byte_perm(b2, b3, 0x0040), 0x5410);
        }
        __syncthreads();
        if (t < 128) {
            const uint32_t* cr = &codes[t * CODE_STRW];
            int sum = 0;
            #pragma unroll
            for (int k = 0; k < 32; k++) sum = __dp4a((int)cr[k], ONEB, sum);
            codes[t * CODE_STRW + 32] = (uint32_t)sum;
        }
        __syncthreads();

        uint32_t a[16];
        #pragma unroll
        for (int kc = 0; kc < 4; kc++)
            ldsm_x4(a[kc * 4], a[kc * 4 + 1], a[kc * 4 + 2], a[kc * 4 + 3],
                    ldA_base + kc * 32);
        int rs_lo = (int)codes[rlo * CODE_STRW + 32];
        int rs_hi = (int)codes[(rlo + 8) * CODE_STRW + 32];
        long growL = (r0 + rlo) * 256, growH = (r0 + rlo + 8) * 256;

        #pragma unroll
        for (int g = 0; g < 4; g++) {
            float al = alsm[g];
            int   zwrs_lo = zwsm[g] * rs_lo, zwrs_hi = zwsm[g] * rs_hi;
            float mn = 1e30f, mx = -1e30f;
            #pragma unroll 4
            for (int ntg = 0; ntg < 8; ntg++) {
                int nt = g * 8 + ntg;
                int C[4] = {0, 0, 0, 0};
                #pragma unroll
                for (int kc = 0; kc < 4; kc++) {
                    uint32_t b0, b1;
                    ldsm_x2(b0, b1, ldB_base + nt * (8 * W_STRB) + kc * 32);
                    mma_s8(C, a[kc * 4], a[kc * 4 + 1], a[kc * 4 + 2], a[kc * 4 + 3],
                           b0, b1);
                }
                int col0 = nt * 8 + 2 * (lane & 3);
                int co0 = cosm[col0], co1 = cosm[col0 + 1];
                float bo0 = bosm[col0], bo1 = bosm[col0 + 1];
                float G0 = __fmaf_rn(__int2float_rn(C[0] + co0 - zwrs_lo), al, bo0);
                float G1 = __fmaf_rn(__int2float_rn(C[1] + co1 - zwrs_lo), al, bo1);
                float G2 = __fmaf_rn(__int2float_rn(C[2] + co0 - zwrs_hi), al, bo0);
                float G3 = __fmaf_rn(__int2float_rn(C[3] + co1 - zwrs_hi), al, bo1);
                *(float2*)&g_G[growL + col0] = make_float2(G0, G1);
                *(float2*)&g_G[growH + col0] = make_float2(G2, G3);
                mn = fminf(mn, fminf(fminf(G0, G1), fminf(G2, G3)));
                mx = fmaxf(mx, fmaxf(fmaxf(G0, G1), fmaxf(G2, G3)));
            }
            mnG[g] = fminf(mnG[g], mn);
            mxG[g] = fmaxf(mxG[g], mx);
        }
        __syncthreads();
    }
    #pragma unroll
    for (int g = 0; g < 4; g++) {
        float mn = mnG[g], mx = mxG[g];
        #pragma unroll
        for (int o = 16; o; o >>= 1) {
            mn = fminf(mn, __shfl_xor_sync(0xffffffffu, mn, o));
            mx = fmaxf(mx, __shfl_xor_sync(0xffffffffu, mx, o));
        }
        if (lane == 0) {
            atomicMin(&g_mm[6 + 2 * g], fenc(mn));
            atomicMax(&g_mm[7 + 2 * g], fenc(mx));
        }
    }
    if (last_block(&g_ctr[1]) && t == 0) { g_ctr[1] = 0u; p2_body(); }
}

// ---------- K5: activations from stored G; fc/ic minmax; last block runs p3 ----------
__global__ void k_act() {
    float rG[4], zG[4], c1[4], c2[4], rA[4], zA[4], sA[4];
    #pragma unroll
    for (int g = 0; g < 4; g++) {
        rG[g] = g_p.rG[g]; zG[g] = g_p.zpG[g];
        c1[g] = g_p.c1G[g]; c2[g] = g_p.c2G[g];
        rA[g] = g_p.rA[g]; zA[g] = g_p.zpA[g];
        sA[g] = g_p.sA[g];
    }
    float scc = g_p.s_c, zcc = g_p.zp_c;
    float mn1 = 1e30f, mx1 = -1e30f, mn2 = 1e30f, mx2 = -1e30f;
    for (long i = blockIdx.x * blockDim.x + threadIdx.x; i < NE / 4;
         i += (long)gridDim.x * blockDim.x) {
        long row = i >> 4;
        int h0 = (int)(i & 15) * 4;
        char4 qc = ((const char4*)g_cq)[i];
        int ccode[4] = {qc.x, qc.y, qc.z, qc.w};
        float acode[4][4];
        #pragma unroll
        for (int g = 0; g < 4; g++) {
            float4 G4 = *(const float4*)&g_G[row * 256 + g * 64 + h0];
            float gv[4] = {G4.x, G4.y, G4.z, G4.w};
            float aLo = (g == 3) ? -1.f : 0.f;
            uint32_t q[4];
            #pragma unroll
            for (int j = 0; j < 4; j++) {
                float cf = quant_qm(gv[j], rG[g], zG[g]);
                float a = fminf(fmaxf(__fmaf_rn(cf, c1[g], c2[g]), aLo), 1.f);
                float code = quant_qm(a, rA[g], zA[g]);
                acode[g][j] = code;
                q[j] = __float_as_uint(__fadd_rn(code, FMG));
            }
            ((uint32_t*)g_act[g])[i] =
                __byte_perm(__byte_perm(q[0], q[1], 0x0040),
                            __byte_perm(q[2], q[3], 0x0040), 0x5410);
        }
        #pragma unroll
        for (int j = 0; j < 4; j++) {
            float fv = __fmul_rn(acode[1][j] - zA[1], sA[1]);
            float iv = __fmul_rn(acode[0][j] - zA[0], sA[0]);
            float gv = __fmul_rn(acode[3][j] - zA[3], sA[3]);
            float cd = __fmul_rn((float)ccode[j] - zcc, scc);
            float fc = __fmul_rn(fv, cd);
            float ic = __fmul_rn(iv, gv);
            mn1 = fminf(mn1, fc); mx1 = fmaxf(mx1, fc);
            mn2 = fminf(mn2, ic); mx2 = fmaxf(mx2, ic);
        }
    }
    block_minmax(mn1, mx1, &g_mm[14], &g_mm[15]);
    block_minmax(mn2, mx2, &g_mm[16], &g_mm[17]);
    if (last_block(&g_ctr[2]) && threadIdx.x == 0) { g_ctr[2] = 0u; p3_body(); }
}

// ---------- K7: minmax of fq(fc)+fq(ic); last block runs p4 ----------
__global__ void k_pre() {
    float sAi = g_p.sA[0], zAi = g_p.zpA[0], sAf = g_p.sA[1], zAf = g_p.zpA[1];
    float sAg = g_p.sA[3], zAg = g_p.zpA[3], scc = g_p.s_c, zcc = g_p.zp_c;
    float sfc = g_p.s_fc, rfc = g_p.r_fc, zfc = g_p.zp_fc;
    float sic = g_p.s_ic, ric = g_p.r_ic, zic = g_p.zp_ic;
    float mn = 1e30f, mx = -1e30f;
    for (long i = blockIdx.x * blockDim.x + threadIdx.x; i < NE / 4;
         i += (long)gridDim.x * blockDim.x) {
        char4 qi = ((const char4*)g_act[0])[i];
        char4 qf = ((const char4*)g_act[1])[i];
        char4 qg = ((const char4*)g_act[3])[i];
        char4 qc = ((const char4*)g_cq)[i];
        int ii[4] = {qi.x, qi.y, qi.z, qi.w}, ff[4] = {qf.x, qf.y, qf.z, qf.w};
        int gg[4] = {qg.x, qg.y, qg.z, qg.w}, cc[4] = {qc.x, qc.y, qc.z, qc.w};
        #pragma unroll
        for (int j = 0; j < 4; j++) {
            float fv = __fmul_rn((float)ff[j] - zAf, sAf);
            float iv = __fmul_rn((float)ii[j] - zAi, sAi);
            float gv = __fmul_rn((float)gg[j] - zAg, sAg);
            float cd = __fmul_rn((float)cc[j] - zcc, scc);
            float fcv = fqvm(__fmul_rn(fv, cd), sfc, rfc, zfc);
            float icv = fqvm(__fmul_rn(iv, gv), sic, ric, zic);
            float pre = __fadd_rn(fcv, icv);
            mn = fminf(mn, pre); mx = fmaxf(mx, pre);
        }
    }
    block_minmax(mn, mx, &g_mm[18], &g_mm[19]);
    if (last_block(&g_ctr[3]) && threadIdx.x == 0) { g_ctr[3] = 0u; p4_body(); }
}

// ---------- K9: c_next + t codes + o*t minmax; last block runs p5 ----------
__global__ void k_cnext(float* __restrict__ out_c) {
    float sAi = g_p.sA[0], zAi = g_p.zpA[0], sAf = g_p.sA[1], zAf = g_p.zpA[1];
    float sAo = g_p.sA[2], zAo = g_p.zpA[2], sAg = g_p.sA[3], zAg = g_p.zpA[3];
    float scc = g_p.s_c, zcc = g_p.zp_c;
    float sfc = g_p.s_fc, rfc = g_p.r_fc, zfc = g_p.zp_fc;
    float sic = g_p.s_ic, ric = g_p.r_ic, zic = g_p.zp_ic;
    float scn = g_p.s_cn, rcn = g_p.r_cn, zcn = g_p.zp_cn;
    float st = g_p.s_t, rt = g_p.r_t, zt = g_p.zp_t;
    float mn = 1e30f, mx = -1e30f;
    for (long i = blockIdx.x * blockDim.x + threadIdx.x; i < NE / 4;
         i += (long)gridDim.x * blockDim.x) {
        char4 qi = ((const char4*)g_act[0])[i];
        char4 qf = ((const char4*)g_act[1])[i];
        char4 qo = ((const char4*)g_act[2])[i];
        char4 qg = ((const char4*)g_act[3])[i];
        char4 qc = ((const char4*)g_cq)[i];
        int ii[4] = {qi.x, qi.y, qi.z, qi.w}, ff[4] = {qf.x, qf.y, qf.z, qf.w};
        int oo[4] = {qo.x, qo.y, qo.z, qo.w}, gg[4] = {qg.x, qg.y, qg.z, qg.w};
        int cc[4] = {qc.x, qc.y, qc.z, qc.w};
        float4 outc;
        float* oc = (float*)&outc;
        char4 tq4;
        int8_t* tqq = (int8_t*)&tq4;
        #pragma unroll
        for (int j = 0; j < 4; j++) {
            float fv = __fmul_rn((float)ff[j] - zAf, sAf);
            float iv = __fmul_rn((float)ii[j] - zAi, sAi);
            float gv = __fmul_rn((float)gg[j] - zAg, sAg);
            float cd = __fmul_rn((float)cc[j] - zcc, scc);
            float fcv = fqvm(__fmul_rn(fv, cd), sfc, rfc, zfc);
            float icv = fqvm(__fmul_rn(iv, gv), sic, ric, zic);
            float pre = __fadd_rn(fcv, icv);
            float cn = fqvm(pre, scn, rcn, zcn);
            oc[j] = cn;
            float tcodef = quant_qm(htanh(cn), rt, zt);
            tqq[j] = (int8_t)(int)tcodef;
            float tv = __fmul_rn(tcodef - zt, st);
            float ov = __fmul_rn((float)oo[j] - zAo, sAo);
            float hp = __fmul_rn(ov, tv);
            mn = fminf(mn, hp); mx = fmaxf(mx, hp);
        }
        ((float4*)out_c)[i] = outc;
        ((char4*)g_tq)[i] = tq4;
    }
    block_minmax(mn, mx, &g_mm[20], &g_mm[21]);
    if (last_block(&g_ctr[4]) && threadIdx.x == 0) { g_ctr[4] = 0u; p5_body(); }
}

// ---------- K11 ----------
__global__ void k_hnext(float* __restrict__ out_h) {
    float sAo = g_p.sA[2], zAo = g_p.zpA[2], st = g_p.s_t, zt = g_p.zp_t;
    float shn = g_p.s_hn, rhn = g_p.r_hn, zhn = g_p.zp_hn;
    for (long i = blockIdx.x * blockDim.x + threadIdx.x; i < NE / 4;
         i += (long)gridDim.x * blockDim.x) {
        char4 qo = ((const char4*)g_act[2])[i];
        char4 qt = ((const char4*)g_tq)[i];
        int oo[4] = {qo.x, qo.y, qo.z, qo.w}, tt[4] = {qt.x, qt.y, qt.z, qt.w};
        float4 outh;
        float* oh = (float*)&outh;
        #pragma unroll
        for (int j = 0; j < 4; j++) {
            float ov = __fmul_rn((float)oo[j] - zAo, sAo);
            float tv = __fmul_rn((float)tt[j] - zt, st);
            oh[j] = fqvm(__fmul_rn(ov, tv), shn, rhn, zhn);
        }
        ((float4*)out_h)[i] = outh;
    }
}

extern "C" void kernel_launch(void* const* d_in, const int* in_sizes, int n_in,
                              void* d_out, int out_size) {
    const float* x  = (const float*)d_in[0];
    const float* h  = (const float*)d_in[1];
    const float* c  = (const float*)d_in[2];
    const float* Wi = (const float*)d_in[3];
    const float* bi = (const float*)d_in[4];
    const float* Wf = (const float*)d_in[5];
    const float* bf = (const float*)d_in[6];
    const float* Wo = (const float*)d_in[7];
    const float* bo = (const float*)d_in[8];
    const float* Wc = (const float*)d_in[9];
    const float* bc = (const float*)d_in[10];
    float* out_h = (float*)d_out;
    float* out_c = (float*)d_out + NE;

    static int attr_done = 0;
    if (!attr_done) {
        cudaFuncSetAttribute(k_gemmA, cudaFuncAttributeMaxDynamicSharedMemorySize, DYN_A);
        attr_done = 1;
    }

    k_init<<<1, 32>>>();
    k_minmax3<<<2048, 256>>>(x, h, c, Wi, bi, Wf, bf, Wo, bo, Wc, bc);
    k_gemmA<<<2048, 256, DYN_A>>>(x, h, c);
    k_act<<<EW_GRID, 256>>>();
    k_pre<<<EW_GRID, 256>>>();
    k_cnext<<<EW_GRID, 256>>>(out_c);
    k_hnext<<<EW_GRID, 256>>>(out_h);
}

// round 16
// speedup vs baseline: 1.1253x; 1.0700x over previous
#include <cuda_runtime.h>
#include <stdint.h>

#define R_TOT 524288
#define NE    33554432
#define ONEB  0x01010101
#define FMG   12582912.0f
#define EW_GRID 2368

struct Params {
    float s_x, zp_x, s_h, zp_h, s_c, zp_c, s_cat, zp_cat;
    float r_x, r_h, r_c, r_cat;
    float alpha[4];
    float bdq[256];
    int   zpw_i[4], zpc_i;
    float sG[4], zpG[4], sA[4], zpA[4];
    float rG[4], rA[4];
    float c1G[4], c2G[4];
    float s_fc, zp_fc, s_ic, zp_ic, s_cn, zp_cn, s_t, zp_t, s_hn, zp_hn;
    float r_fc, r_ic, r_cn, r_t, r_hn;
};

__device__ Params   g_p;
__device__ unsigned g_mm[22];
__device__ unsigned g_ctr[5];
__device__ int8_t   g_wq[256 * 128];
__device__ int      g_const[256];
__device__ float    g_G[134217728];      // gate pre-activations [row][256] (512 MB)
__device__ int8_t   g_act[4][NE];
__device__ int8_t   g_cq[NE];
__device__ int8_t   g_tq[NE];

// ---------- helpers ----------
__device__ __forceinline__ unsigned fenc(float f) {
    unsigned u = __float_as_uint(f);
    return (u & 0x80000000u) ? ~u : (u | 0x80000000u);
}
__device__ __forceinline__ float fdec(unsigned u) {
    return __uint_as_float((u & 0x80000000u) ? (u & 0x7fffffffu) : ~u);
}
__device__ __forceinline__ float clip128(float x) { return fminf(fmaxf(x, -128.f), 127.f); }
__device__ __forceinline__ float quant_qm(float v, float rs, float zp) {
    float x = clip128(__fmaf_rn(v, rs, zp));
    return __fadd_rn(__fadd_rn(x, FMG), -FMG);
}
__device__ __forceinline__ uint32_t quant_qb(float v, float rs, float zp) {
    float x = clip128(__fmaf_rn(v, rs, zp));
    return __float_as_uint(__fadd_rn(x, FMG));
}
__device__ __forceinline__ float fqvm(float v, float s, float rs, float zp) {
    return __fmul_rn(quant_qm(v, rs, zp) - zp, s);
}
__device__ __forceinline__ void mkparams(float mnr, float mxr, float* s, float* zp) {
    float mn = fminf(mnr, 0.f), mx = fmaxf(mxr, 0.f);
    float sc = fmaxf(__fdiv_rn(mx - mn, 255.f), 1e-8f);
    float z  = rintf(-128.f - __fdiv_rn(mn, sc));
    *s = sc; *zp = fminf(fmaxf(z, -128.f), 127.f);
}
#define HSIG_C 0.16666667f
__device__ __forceinline__ float hsig(float v) {
    return fminf(fmaxf(__fadd_rn(__fmul_rn(v, HSIG_C), 0.5f), 0.f), 1.f);
}
__device__ __forceinline__ float htanh(float v) { return fminf(fmaxf(v, -1.f), 1.f); }

__device__ __forceinline__ void block_minmax(float mn, float mx, unsigned* gmin, unsigned* gmax) {
    #pragma unroll
    for (int o = 16; o; o >>= 1) {
        mn = fminf(mn, __shfl_xor_sync(0xffffffffu, mn, o));
        mx = fmaxf(mx, __shfl_xor_sync(0xffffffffu, mx, o));
    }
    __shared__ float smn[8], smx[8];
    int w = threadIdx.x >> 5, nw = blockDim.x >> 5;
    __syncthreads();
    if ((threadIdx.x & 31) == 0) { smn[w] = mn; smx[w] = mx; }
    __syncthreads();
    if (threadIdx.x == 0) {
        for (int i = 1; i < nw; i++) { mn = fminf(mn, smn[i]); mx = fmaxf(mx, smx[i]); }
        atomicMin(gmin, fenc(mn)); atomicMax(gmax, fenc(mx));
    }
    __syncthreads();
}
__device__ __forceinline__ float2 block_reduce_pair(float mn, float mx) {
    #pragma unroll
    for (int o = 16; o; o >>= 1) {
        mn = fminf(mn, __shfl_xor_sync(0xffffffffu, mn, o));
        mx = fmaxf(mx, __shfl_xor_sync(0xffffffffu, mx, o));
    }
    __shared__ float smn[8], smx[8];
    __shared__ float2 res;
    int w = threadIdx.x >> 5, nw = blockDim.x >> 5;
    __syncthreads();
    if ((threadIdx.x & 31) == 0) { smn[w] = mn; smx[w] = mx; }
    __syncthreads();
    if (threadIdx.x == 0) {
        for (int i = 1; i < nw; i++) { mn = fminf(mn, smn[i]); mx = fmaxf(mx, smx[i]); }
        res = make_float2(mn, mx);
    }
    __syncthreads();
    return res;
}
__device__ __forceinline__ bool last_block(unsigned* ctr) {
    __shared__ int amLast;
    __threadfence();
    if (threadIdx.x == 0)
        amLast = (atomicAdd(ctr, 1u) == gridDim.x - 1u);
    __syncthreads();
    return amLast != 0;
}

__device__ __forceinline__ void mma_s8(int* c, uint32_t a0, uint32_t a1, uint32_t a2,
                                       uint32_t a3, uint32_t b0, uint32_t b1) {
    asm volatile(
        "mma.sync.aligned.m16n8k32.row.col.s32.s8.s8.s32 "
        "{%0,%1,%2,%3}, {%4,%5,%6,%7}, {%8,%9}, {%0,%1,%2,%3};\n"
        : "+r"(c[0]), "+r"(c[1]), "+r"(c[2]), "+r"(c[3])
        : "r"(a0), "r"(a1), "r"(a2), "r"(a3), "r"(b0), "r"(b1));
}
__device__ __forceinline__ void ldsm_x4(uint32_t& r0, uint32_t& r1, uint32_t& r2,
                                        uint32_t& r3, uint32_t addr) {
    asm volatile("ldmatrix.sync.aligned.m8n8.x4.shared.b16 {%0,%1,%2,%3}, [%4];"
                 : "=r"(r0), "=r"(r1), "=r"(r2), "=r"(r3) : "r"(addr));
}
__device__ __forceinline__ void ldsm_x2(uint32_t& r0, uint32_t& r1, uint32_t addr) {
    asm volatile("ldmatrix.sync.aligned.m8n8.x2.shared.b16 {%0,%1}, [%2];"
                 : "=r"(r0), "=r"(r1) : "r"(addr));
}

// ---------- scalar param bodies ----------
__device__ void p2_body() {
    for (int g = 0; g < 4; g++) {
        float mn = fdec(g_mm[6 + 2 * g]), mx = fdec(g_mm[7 + 2 * g]);
        mkparams(mn, mx, &g_p.sG[g], &g_p.zpG[g]);
        g_p.rG[g] = __fdiv_rn(1.f, g_p.sG[g]);
        float lo = fqvm(mn, g_p.sG[g], g_p.rG[g], g_p.zpG[g]);
        float hi = fqvm(mx, g_p.sG[g], g_p.rG[g], g_p.zpG[g]);
        float amin, amax;
        if (g < 3) { amin = hsig(lo); amax = hsig(hi); }
        else       { amin = htanh(lo); amax = htanh(hi); }
        mkparams(amin, amax, &g_p.sA[g], &g_p.zpA[g]);
        g_p.rA[g] = __fdiv_rn(1.f, g_p.sA[g]);
        if (g < 3) {
            g_p.c1G[g] = __fmul_rn(g_p.sG[g], HSIG_C);
            g_p.c2G[g] = __fadd_rn(0.5f, -__fmul_rn(g_p.zpG[g], g_p.c1G[g]));
        } else {
            g_p.c1G[g] = g_p.sG[g];
            g_p.c2G[g] = -__fmul_rn(g_p.zpG[g], g_p.sG[g]);
        }
    }
}
__device__ void p3_body() {
    mkparams(fdec(g_mm[14]), fdec(g_mm[15]), &g_p.s_fc, &g_p.zp_fc);
    mkparams(fdec(g_mm[16]), fdec(g_mm[17]), &g_p.s_ic, &g_p.zp_ic);
    g_p.r_fc = __fdiv_rn(1.f, g_p.s_fc);
    g_p.r_ic = __fdiv_rn(1.f, g_p.s_ic);
}
__device__ void p4_body() {
    float mn = fdec(g_mm[18]), mx = fdec(g_mm[19]);
    mkparams(mn, mx, &g_p.s_cn, &g_p.zp_cn);
    g_p.r_cn = __fdiv_rn(1.f, g_p.s_cn);
    float lo = htanh(fqvm(mn, g_p.s_cn, g_p.r_cn, g_p.zp_cn));
    float hi = htanh(fqvm(mx, g_p.s_cn, g_p.r_cn, g_p.zp_cn));
    mkparams(lo, hi, &g_p.s_t, &g_p.zp_t);
    g_p.r_t = __fdiv_rn(1.f, g_p.s_t);
}
__device__ void p5_body() {
    mkparams(fdec(g_mm[20]), fdec(g_mm[21]), &g_p.s_hn, &g_p.zp_hn);
    g_p.r_hn = __fdiv_rn(1.f, g_p.s_hn);
}

// ---------- K0 ----------
__global__ void k_init() {
    int t = threadIdx.x;
    if (t < 11) { g_mm[2 * t] = fenc(1e30f); g_mm[2 * t + 1] = fenc(-1e30f); }
    if (t < 5) g_ctr[t] = 0u;
}

// ---------- K1: minmax of x,h,c ; last block runs the params body ----------
__global__ void k_minmax3(const float* __restrict__ x, const float* __restrict__ h,
                          const float* __restrict__ c,
                          const float* __restrict__ Wi, const float* __restrict__ bi,
                          const float* __restrict__ Wf, const float* __restrict__ bf,
                          const float* __restrict__ Wo, const float* __restrict__ bo,
                          const float* __restrict__ Wc, const float* __restrict__ bc) {
    const float* arrs[3] = {x, h, c};
    for (int a = 0; a < 3; a++) {
        float mn = 1e30f, mx = -1e30f;
        const float4* p = (const float4*)arrs[a];
        for (long i = blockIdx.x * blockDim.x + threadIdx.x; i < NE / 4;
             i += (long)gridDim.x * blockDim.x) {
            float4 v = p[i];
            mn = fminf(fminf(fminf(mn, v.x), v.y), fminf(v.z, v.w));
            mx = fmaxf(fmaxf(fmaxf(mx, v.x), v.y), fmaxf(v.z, v.w));
        }
        block_minmax(mn, mx, &g_mm[2 * a], &g_mm[2 * a + 1]);
    }
    if (!last_block(&g_ctr[0])) return;
    __shared__ float sw, zw, rw, sb, zb, rb_;
    int t = threadIdx.x;
    if (t == 0) {
        g_ctr[0] = 0u;
        mkparams(fdec(g_mm[0]), fdec(g_mm[1]), &g_p.s_x, &g_p.zp_x);
        mkparams(fdec(g_mm[2]), fdec(g_mm[3]), &g_p.s_h, &g_p.zp_h);
        mkparams(fdec(g_mm[4]), fdec(g_mm[5]), &g_p.s_c, &g_p.zp_c);
        g_p.r_x = __fdiv_rn(1.f, g_p.s_x);
        g_p.r_h = __fdiv_rn(1.f, g_p.s_h);
        g_p.r_c = __fdiv_rn(1.f, g_p.s_c);
        float xlo = fqvm(fdec(g_mm[0]), g_p.s_x, g_p.r_x, g_p.zp_x);
        float xhi = fqvm(fdec(g_mm[1]), g_p.s_x, g_p.r_x, g_p.zp_x);
        float hlo = fqvm(fdec(g_mm[2]), g_p.s_h, g_p.r_h, g_p.zp_h);
        float hhi = fqvm(fdec(g_mm[3]), g_p.s_h, g_p.r_h, g_p.zp_h);
        mkparams(fminf(xlo, hlo), fmaxf(xhi, hhi), &g_p.s_cat, &g_p.zp_cat);
        g_p.r_cat = __fdiv_rn(1.f, g_p.s_cat);
        g_p.zpc_i = (int)g_p.zp_cat;
    }
    __syncthreads();
    const float* Wg[4] = {Wi, Wf, Wo, Wc};
    const float* bg[4] = {bi, bf, bo, bc};
    for (int g = 0; g < 4; g++) {
        float mn = 1e30f, mx = -1e30f;
        for (int i = t; i < 8192; i += 256) {
            float v = Wg[g][i];
            mn = fminf(mn, v); mx = fmaxf(mx, v);
        }
        float2 m = block_reduce_pair(mn, mx);
        if (t == 0) {
            mkparams(m.x, m.y, &sw, &zw);
            rw = __fdiv_rn(1.f, sw);
            g_p.alpha[g] = __fmul_rn(g_p.s_cat, sw);
            g_p.zpw_i[g] = (int)zw;
        }
        __syncthreads();
        for (int i = t; i < 8192; i += 256)
            g_wq[g * 8192 + i] = (int8_t)(int)quant_qm(Wg[g][i], rw, zw);
        mn = (t < 64) ? bg[g][t] : 1e30f;
        mx = (t < 64) ? bg[g][t] : -1e30f;
        m = block_reduce_pair(mn, mx);
        if (t == 0) { mkparams(m.x, m.y, &sb, &zb); rb_ = __fdiv_rn(1.f, sb); }
        __syncthreads();
        if (t < 64) g_p.bdq[g * 64 + t] = fqvm(bg[g][t], sb, rb_, zb);
        __syncthreads();
    }
    {
        int s = 0;
        const int8_t* wr = &g_wq[t * 128];
        for (int k = 0; k < 128; k++) s += wr[k];
        int g = t >> 6;
        g_const[t] = -g_p.zpc_i * s + 128 * g_p.zpc_i * g_p.zpw_i[g];
    }
}

#define W_BYTES   36864
#define W_STRB    144
#define CODE_STRW 36
#define DYN_A     (W_BYTES + 128 * CODE_STRW * 4)

// ---------- K3: single GEMM pass; last block runs p2 ----------
__global__ void __launch_bounds__(256) k_gemmA(const float* __restrict__ X,
                                               const float* __restrict__ H,
                                               const float* __restrict__ Cp) {
    extern __shared__ uint8_t dyn[];
    uint32_t* codes = (uint32_t*)(dyn + W_BYTES);
    __shared__ int   cosm[256];
    __shared__ float bosm[256];
    __shared__ float alsm[4];
    __shared__ int   zwsm[4];
    int t = threadIdx.x, lane = t & 31, w = t >> 5;

    {
        const uint4* wsrc = (const uint4*)&g_wq[t * 128];
        uint4* wdst = (uint4*)(dyn + t * W_STRB);
        #pragma unroll
        for (int i = 0; i < 8; i++) wdst[i] = wsrc[i];
    }
    cosm[t] = g_const[t];
    bosm[t] = g_p.bdq[t];
    if (t < 4) { alsm[t] = g_p.alpha[t]; zwsm[t] = g_p.zpw_i[t]; }

    float sx = g_p.s_x, rx = g_p.r_x, zx = g_p.zp_x;
    float sh = g_p.s_h, rh = g_p.r_h, zh = g_p.zp_h;
    float nzx = -__fmul_rn(zx, sx), nzh = -__fmul_rn(zh, sh);
    float rc = g_p.r_cat, zc = g_p.zp_cat;
    float rcc = g_p.r_c, zcc = g_p.zp_c;
    const float4* X4 = (const float4*)X;
    const float4* H4 = (const float4*)H;
    const float4* C4 = (const float4*)Cp;

    uint32_t Waddr = (uint32_t)__cvta_generic_to_shared(dyn);
    uint32_t Caddr = (uint32_t)__cvta_generic_to_shared(codes);
    uint32_t ldB_base = Waddr + (lane & 7) * W_STRB + ((lane >> 3) & 1) * 16;
    uint32_t ldA_base = Caddr + (w * 16 + (lane & 15)) * 144 + (lane >> 4) * 16;
    int rlo = w * 16 + (lane >> 2);

    float mnG[4], mxG[4];
    #pragma unroll
    for (int g = 0; g < 4; g++) { mnG[g] = 1e30f; mxG[g] = -1e30f; }
    __syncthreads();

    for (int tile = blockIdx.x; tile < R_TOT / 128; tile += gridDim.x) {
        long r0 = (long)tile * 128;
        #pragma unroll
        for (int i = 0; i < 8; i++) {
            int idx = t + i * 256;
            float4 v = C4[r0 * 16 + idx];
            uint32_t b0 = quant_qb(v.x, rcc, zcc);
            uint32_t b1 = quant_qb(v.y, rcc, zcc);
            uint32_t b2 = quant_qb(v.z, rcc, zcc);
            uint32_t b3 = quant_qb(v.w, rcc, zcc);
            ((uint32_t*)g_cq)[r0 * 16 + idx] =
                __byte_perm(__byte_perm(b0, b1, 0x0040),
                            __byte_perm(b2, b3, 0x0040), 0x5410);
        }
        #pragma unroll 4
        for (int rr = 0; rr < 16; rr++) {
            int lrow = w * 16 + rr;
            long row = r0 + lrow;
            float4 v = (lane < 16) ? X4[row * 16 + lane] : H4[row * 16 + lane - 16];
            float s0 = (lane < 16) ? sx : sh;
            float r0s = (lane < 16) ? rx : rh;
            float z0 = (lane < 16) ? zx : zh;
            float nz0 = (lane < 16) ? nzx : nzh;
            float c0 = quant_qm(v.x, r0s, z0), c1 = quant_qm(v.y, r0s, z0);
            float c2 = quant_qm(v.z, r0s, z0), c3 = quant_qm(v.w, r0s, z0);
            uint32_t b0 = quant_qb(__fmaf_rn(c0, s0, nz0), rc, zc);
            uint32_t b1 = quant_qb(__fmaf_rn(c1, s0, nz0), rc, zc);
            uint32_t b2 = quant_qb(__fmaf_rn(c2, s0, nz0), rc, zc);
            uint32_t b3 = quant_qb(__fmaf_rn(c3, s0, nz0), rc, zc);
            codes[lrow * CODE_STRW + lane] =
                __byte_perm(__byte_perm(b0, b1, 0x0040),
                            __byte_perm(b2, b3, 0x0040), 0x5410);
        }
        __syncthreads();
        if (t < 128) {
            const uint32_t* cr = &codes[t * CODE_STRW];
            int sum = 0;
            #pragma unroll
            for (int k = 0; k < 32; k++) sum = __dp4a((int)cr[k], ONEB, sum);
            codes[t * CODE_STRW + 32] = (uint32_t)sum;
        }
        __syncthreads();

        uint32_t a[16];
        #pragma unroll
        for (int kc = 0; kc < 4; kc++)
            ldsm_x4(a[kc * 4], a[kc * 4 + 1], a[kc * 4 + 2], a[kc * 4 + 3],
                    ldA_base + kc * 32);
        int rs_lo = (int)codes[rlo * CODE_STRW + 32];
        int rs_hi = (int)codes[(rlo + 8) * CODE_STRW + 32];
        long growL = (r0 + rlo) * 256, growH = (r0 + rlo + 8) * 256;

        #pragma unroll
        for (int g = 0; g < 4; g++) {
            float al = alsm[g];
            int   zwrs_lo = zwsm[g] * rs_lo, zwrs_hi = zwsm[g] * rs_hi;
            float mn = 1e30f, mx = -1e30f;
            #pragma unroll 4
            for (int ntg = 0; ntg < 8; ntg++) {
                int nt = g * 8 + ntg;
                int C[4] = {0, 0, 0, 0};
                #pragma unroll
                for (int kc = 0; kc < 4; kc++) {
                    uint32_t b0, b1;
                    ldsm_x2(b0, b1, ldB_base + nt * (8 * W_STRB) + kc * 32);
                    mma_s8(C, a[kc * 4], a[kc * 4 + 1], a[kc * 4 + 2], a[kc * 4 + 3],
                           b0, b1);
                }
                int col0 = nt * 8 + 2 * (lane & 3);
                int co0 = cosm[col0], co1 = cosm[col0 + 1];
                float bo0 = bosm[col0], bo1 = bosm[col0 + 1];
                float G0 = __fmaf_rn(__int2float_rn(C[0] + co0 - zwrs_lo), al, bo0);
                float G1 = __fmaf_rn(__int2float_rn(C[1] + co1 - zwrs_lo), al, bo1);
                float G2 = __fmaf_rn(__int2float_rn(C[2] + co0 - zwrs_hi), al, bo0);
                float G3 = __fmaf_rn(__int2float_rn(C[3] + co1 - zwrs_hi), al, bo1);
                *(float2*)&g_G[growL + col0] = make_float2(G0, G1);
                *(float2*)&g_G[growH + col0] = make_float2(G2, G3);
                mn = fminf(mn, fminf(fminf(G0, G1), fminf(G2, G3)));
                mx = fmaxf(mx, fmaxf(fmaxf(G0, G1), fmaxf(G2, G3)));
            }
            mnG[g] = fminf(mnG[g], mn);
            mxG[g] = fmaxf(mxG[g], mx);
        }
        __syncthreads();
    }
    #pragma unroll
    for (int g = 0; g < 4; g++) {
        float mn = mnG[g], mx = mxG[g];
        #pragma unroll
        for (int o = 16; o; o >>= 1) {
            mn = fminf(mn, __shfl_xor_sync(0xffffffffu, mn, o));
            mx = fmaxf(mx, __shfl_xor_sync(0xffffffffu, mx, o));
        }
        if (lane == 0) {
            atomicMin(&g_mm[6 + 2 * g], fenc(mn));
            atomicMax(&g_mm[7 + 2 * g], fenc(mx));
        }
    }
    if (last_block(&g_ctr[1]) && t == 0) { g_ctr[1] = 0u; p2_body(); }
}

// ---------- K5: activations from stored G (x2 batched); last block runs p3 ----------
__global__ void k_act() {
    float rG[4], zG[4], c1[4], c2[4], rA[4], zA[4], sA[4];
    #pragma unroll
    for (int g = 0; g < 4; g++) {
        rG[g] = g_p.rG[g]; zG[g] = g_p.zpG[g];
        c1[g] = g_p.c1G[g]; c2[g] = g_p.c2G[g];
        rA[g] = g_p.rA[g]; zA[g] = g_p.zpA[g];
        sA[g] = g_p.sA[g];
    }
    float scc = g_p.s_c, zcc = g_p.zp_c;
    float mn1 = 1e30f, mx1 = -1e30f, mn2 = 1e30f, mx2 = -1e30f;
    // each iteration: 8 elements = 2 uint32 code-words (same row; h0 and h0+4)
    for (long j = blockIdx.x * blockDim.x + threadIdx.x; j < NE / 8;
         j += (long)gridDim.x * blockDim.x) {
        long i0 = j * 2;
        long row = i0 >> 4;
        int h0 = (int)(i0 & 15) * 4;
        // front-batch all loads: 1x uint2 + 8x float4
        uint2 qc2 = ((const uint2*)g_cq)[j];
        float4 GA[4], GB[4];
        #pragma unroll
        for (int g = 0; g < 4; g++) {
            const float4* gp = (const float4*)&g_G[row * 256 + g * 64 + h0];
            GA[g] = gp[0];
            GB[g] = gp[1];
        }
        float acodeA[4][4], acodeB[4][4];
        #pragma unroll
        for (int g = 0; g < 4; g++) {
            float aLo = (g == 3) ? -1.f : 0.f;
            float gvA[4] = {GA[g].x, GA[g].y, GA[g].z, GA[g].w};
            float gvB[4] = {GB[g].x, GB[g].y, GB[g].z, GB[g].w};
            uint32_t qA[4], qB[4];
            #pragma unroll
            for (int jj = 0; jj < 4; jj++) {
                float cfA = quant_qm(gvA[jj], rG[g], zG[g]);
                float aA = fminf(fmaxf(__fmaf_rn(cfA, c1[g], c2[g]), aLo), 1.f);
                float codeA = quant_qm(aA, rA[g], zA[g]);
                acodeA[g][jj] = codeA;
                qA[jj] = __float_as_uint(__fadd_rn(codeA, FMG));
                float cfB = quant_qm(gvB[jj], rG[g], zG[g]);
                float aB = fminf(fmaxf(__fmaf_rn(cfB, c1[g], c2[g]), aLo), 1.f);
                float codeB = quant_qm(aB, rA[g], zA[g]);
                acodeB[g][jj] = codeB;
                qB[jj] = __float_as_uint(__fadd_rn(codeB, FMG));
            }
            uint2 out;
            out.x = __byte_perm(__byte_perm(qA[0], qA[1], 0x0040),
                                __byte_perm(qA[2], qA[3], 0x0040), 0x5410);
            out.y = __byte_perm(__byte_perm(qB[0], qB[1], 0x0040),
                                __byte_perm(qB[2], qB[3], 0x0040), 0x5410);
            ((uint2*)g_act[g])[j] = out;
        }
        #pragma unroll
        for (int half = 0; half < 2; half++) {
            uint32_t wc = half ? qc2.y : qc2.x;
            #pragma unroll
            for (int jj = 0; jj < 4; jj++) {
                float ai = half ? acodeB[0][jj] : acodeA[0][jj];
                float af = half ? acodeB[1][jj] : acodeA[1][jj];
                float ag = half ? acodeB[3][jj] : acodeA[3][jj];
                float fv = __fmul_rn(af - zA[1], sA[1]);
                float iv = __fmul_rn(ai - zA[0], sA[0]);
                float gv = __fmul_rn(ag - zA[3], sA[3]);
                float cd = __fmul_rn((float)(int)(int8_t)(wc >> (8 * jj)) - zcc, scc);
                float fc = __fmul_rn(fv, cd);
                float ic = __fmul_rn(iv, gv);
                mn1 = fminf(mn1, fc); mx1 = fmaxf(mx1, fc);
                mn2 = fminf(mn2, ic); mx2 = fmaxf(mx2, ic);
            }
        }
    }
    block_minmax(mn1, mx1, &g_mm[14], &g_mm[15]);
    block_minmax(mn2, mx2, &g_mm[16], &g_mm[17]);
    if (last_block(&g_ctr[2]) && threadIdx.x == 0) { g_ctr[2] = 0u; p3_body(); }
}

// ---------- K7: minmax of fq(fc)+fq(ic); last block runs p4 ----------
__global__ void k_pre() {
    float sAi = g_p.sA[0], zAi = g_p.zpA[0], sAf = g_p.sA[1], zAf = g_p.zpA[1];
    float sAg = g_p.sA[3], zAg = g_p.zpA[3], scc = g_p.s_c, zcc = g_p.zp_c;
    float sfc = g_p.s_fc, rfc = g_p.r_fc, zfc = g_p.zp_fc;
    float sic = g_p.s_ic, ric = g_p.r_ic, zic = g_p.zp_ic;
    float mn = 1e30f, mx = -1e30f;
    for (long i = blockIdx.x * blockDim.x + threadIdx.x; i < NE / 4;
         i += (long)gridDim.x * blockDim.x) {
        char4 qi = ((const char4*)g_act[0])[i];
        char4 qf = ((const char4*)g_act[1])[i];
        char4 qg = ((const char4*)g_act[3])[i];
        char4 qc = ((const char4*)g_cq)[i];
        int ii[4] = {qi.x, qi.y, qi.z, qi.w}, ff[4] = {qf.x, qf.y, qf.z, qf.w};
        int gg[4] = {qg.x, qg.y, qg.z, qg.w}, cc[4] = {qc.x, qc.y, qc.z, qc.w};
        #pragma unroll
        for (int j = 0; j < 4; j++) {
            float fv = __fmul_rn((float)ff[j] - zAf, sAf);
            float iv = __fmul_rn((float)ii[j] - zAi, sAi);
            float gv = __fmul_rn((float)gg[j] - zAg, sAg);
            float cd = __fmul_rn((float)cc[j] - zcc, scc);
            float fcv = fqvm(__fmul_rn(fv, cd), sfc, rfc, zfc);
            float icv = fqvm(__fmul_rn(iv, gv), sic, ric, zic);
            float pre = __fadd_rn(fcv, icv);
            mn = fminf(mn, pre); mx = fmaxf(mx, pre);
        }
    }
    block_minmax(mn, mx, &g_mm[18], &g_mm[19]);
    if (last_block(&g_ctr[3]) && threadIdx.x == 0) { g_ctr[3] = 0u; p4_body(); }
}

// ---------- K9: c_next + t codes + o*t minmax; last block runs p5 ----------
__global__ void k_cnext(float* __restrict__ out_c) {
    float sAi = g_p.sA[0], zAi = g_p.zpA[0], sAf = g_p.sA[1], zAf = g_p.zpA[1];
    float sAo = g_p.sA[2], zAo = g_p.zpA[2], sAg = g_p.sA[3], zAg = g_p.zpA[3];
    float scc = g_p.s_c, zcc = g_p.zp_c;
    float sfc = g_p.s_fc, rfc = g_p.r_fc, zfc = g_p.zp_fc;
    float sic = g_p.s_ic, ric = g_p.r_ic, zic = g_p.zp_ic;
    float scn = g_p.s_cn, rcn = g_p.r_cn, zcn = g_p.zp_cn;
    float st = g_p.s_t, rt = g_p.r_t, zt = g_p.zp_t;
    float mn = 1e30f, mx = -1e30f;
    for (long i = blockIdx.x * blockDim.x + threadIdx.x; i < NE / 4;
         i += (long)gridDim.x * blockDim.x) {
        char4 qi = ((const char4*)g_act[0])[i];
        char4 qf = ((const char4*)g_act[1])[i];
        char4 qo = ((const char4*)g_act[2])[i];
        char4 qg = ((const char4*)g_act[3])[i];
        char4 qc = ((const char4*)g_cq)[i];
        int ii[4] = {qi.x, qi.y, qi.z, qi.w}, ff[4] = {qf.x, qf.y, qf.z, qf.w};
        int oo[4] = {qo.x, qo.y, qo.z, qo.w}, gg[4] = {qg.x, qg.y, qg.z, qg.w};
        int cc[4] = {qc.x, qc.y, qc.z, qc.w};
        float4 outc;
        float* oc = (float*)&outc;
        char4 tq4;
        int8_t* tqq = (int8_t*)&tq4;
        #pragma unroll
        for (int j = 0; j < 4; j++) {
            float fv = __fmul_rn((float)ff[j] - zAf, sAf);
            float iv = __fmul_rn((float)ii[j] - zAi, sAi);
            float gv = __fmul_rn((float)gg[j] - zAg, sAg);
            float cd = __fmul_rn((float)cc[j] - zcc, scc);
            float fcv = fqvm(__fmul_rn(fv, cd), sfc, rfc, zfc);
            float icv = fqvm(__fmul_rn(iv, gv), sic, ric, zic);
            float pre = __fadd_rn(fcv, icv);
            float cn = fqvm(pre, scn, rcn, zcn);
            oc[j] = cn;
            float tcodef = quant_qm(htanh(cn), rt, zt);
            tqq[j] = (int8_t)(int)tcodef;
            float tv = __fmul_rn(tcodef - zt, st);
            float ov = __fmul_rn((float)oo[j] - zAo, sAo);
            float hp = __fmul_rn(ov, tv);
            mn = fminf(mn, hp); mx = fmaxf(mx, hp);
        }
        ((float4*)out_c)[i] = outc;
        ((char4*)g_tq)[i] = tq4;
    }
    block_minmax(mn, mx, &g_mm[20], &g_mm[21]);
    if (last_block(&g_ctr[4]) && threadIdx.x == 0) { g_ctr[4] = 0u; p5_body(); }
}

// ---------- K11 ----------
__global__ void k_hnext(float* __restrict__ out_h) {
    float sAo = g_p.sA[2], zAo = g_p.zpA[2], st = g_p.s_t, zt = g_p.zp_t;
    float shn = g_p.s_hn, rhn = g_p.r_hn, zhn = g_p.zp_hn;
    for (long i = blockIdx.x * blockDim.x + threadIdx.x; i < NE / 4;
         i += (long)gridDim.x * blockDim.x) {
        char4 qo = ((const char4*)g_act[2])[i];
        char4 qt = ((const char4*)g_tq)[i];
        int oo[4] = {qo.x, qo.y, qo.z, qo.w}, tt[4] = {qt.x, qt.y, qt.z, qt.w};
        float4 outh;
        float* oh = (float*)&outh;
        #pragma unroll
        for (int j = 0; j < 4; j++) {
            float ov = __fmul_rn((float)oo[j] - zAo, sAo);
            float tv = __fmul_rn((float)tt[j] - zt, st);
            oh[j] = fqvm(__fmul_rn(ov, tv), shn, rhn, zhn);
        }
        ((float4*)out_h)[i] = outh;
    }
}

extern "C" void kernel_launch(void* const* d_in, const int* in_sizes, int n_in,
                              void* d_out, int out_size) {
    const float* x  = (const float*)d_in[0];
    const float* h  = (const float*)d_in[1];
    const float* c  = (const float*)d_in[2];
    const float* Wi = (const float*)d_in[3];
    const float* bi = (const float*)d_in[4];
    const float* Wf = (const float*)d_in[5];
    const float* bf = (const float*)d_in[6];
    const float* Wo = (const float*)d_in[7];
    const float* bo = (const float*)d_in[8];
    const float* Wc = (const float*)d_in[9];
    const float* bc = (const float*)d_in[10];
    float* out_h = (float*)d_out;
    float* out_c = (float*)d_out + NE;

    static int attr_done = 0;
    if (!attr_done) {
        cudaFuncSetAttribute(k_gemmA, cudaFuncAttributeMaxDynamicSharedMemorySize, DYN_A);
        attr_done = 1;
    }

    k_init<<<1, 32>>>();
    k_minmax3<<<2048, 256>>>(x, h, c, Wi, bi, Wf, bf, Wo, bo, Wc, bc);
    k_gemmA<<<2048, 256, DYN_A>>>(x, h, c);
    k_act<<<EW_GRID, 256>>>();
    k_pre<<<EW_GRID, 256>>>();
    k_cnext<<<EW_GRID, 256>>>(out_c);
    k_hnext<<<EW_GRID, 256>>>(out_h);
}